// round 10
// baseline (speedup 1.0000x reference)
#include <cuda_runtime.h>

// predictor_interp2d: nearest-neighbor gather from N=1024 points onto a 256x256 grid.
// d_in[0] = R_pc  [B=2, C=4, N=1024] float32
// d_in[1] = XY_pc [B=2, 2, N=1024]   float32
// d_out   = R_grd [B=2, C=4, 256, 256] float32
//
// Single fused kernel, 256 blocks x 1024 threads, 2 blocks/SM (~88% occupancy).
// Each block owns a 512-cell region (4x2 bins of 8x8 cells) and redundantly
// bins all 1024 points of its batch into a block-local 32x32 CSR in shared
// memory (1 point/thread), staging R alongside. The 5x5-bin neighborhood scan
// (coverage radius 2/32 = 0.0625, miss prob ~3.5e-6/cell) is SPLIT: warps 0-15
// scan rows yb<=by of their cell's neighborhood, warps 16-31 scan rows yb>by
// for the same cells; partial packed keys merge through smem. The rare
// remainder falls back to a rounding-safe expanding-ring loop on part-0 warps.
//
// Argmin is branch-free: key = (ordered_uint(d2) << 32) | point_index, reduced
// with u64 min == (min d2, then min index) == jnp.argmin first-min semantics.
// d2 uses the EXACT reference arithmetic (bit-matched since R2), so the result
// is bit-identical and bin scatter order is irrelevant.

#define NPTS  1024
#define NB    32
#define BINW  0.03125f

__global__ __launch_bounds__(1024, 2)
void nn_fused(const float* __restrict__ XY,
              const float* __restrict__ R,
              float* __restrict__ out) {
    __shared__ float4 spts[NPTS];              // {px, py, s, idx-bits}, bin-ordered
    __shared__ int    soff[NB*NB + 1];         // CSR offsets
    __shared__ int    scnt[NB*NB];             // bin counts
    __shared__ int    scur[NB*NB];             // scatter cursors
    __shared__ int    swsum[32];               // per-warp scan partials
    __shared__ float  sR[4 * NPTS];            // staged field values (16 KB)
    __shared__ unsigned long long skey[512];   // part-1 partial keys (4 KB)

    const int t   = threadIdx.x;
    const int b   = blockIdx.x >> 7;           // 128 regions per batch
    const int reg = blockIdx.x & 127;          // region = 32x16 cells (4x2 bins)

    // ---- Phase 1: block-local binning of all 1024 points (1 per thread) ----
    const float* xy = XY + b * (2 * NPTS);
    const float* Rb = R  + b * (4 * NPTS);

    scnt[t] = 0;
    scur[t] = 0;

    // Stage R to smem (coalesced; latency overlapped with binning below).
    #pragma unroll
    for (int c = 0; c < 4; ++c)
        sR[c * NPTS + t] = Rb[c * NPTS + t];

    __syncthreads();

    const float x = xy[t];
    const float y = xy[NPTS + t];
    const int bxx = min(max((int)(x * 32.0f), 0), NB - 1);
    const int byy = min(max((int)(y * 32.0f), 0), NB - 1);
    const int pbin = byy * NB + bxx;
    atomicAdd(&scnt[pbin], 1);
    __syncthreads();

    // 1024-wide exclusive scan: warp shfl scan + 32-partial warp-0 scan.
    {
        const int v = scnt[t];
        int incl = v;
        #pragma unroll
        for (int d = 1; d < 32; d <<= 1) {
            const int n = __shfl_up_sync(0xffffffffu, incl, d);
            if ((t & 31) >= d) incl += n;
        }
        if ((t & 31) == 31) swsum[t >> 5] = incl;
        __syncthreads();
        if (t < 32) {
            const int w = swsum[t];
            int iw = w;
            #pragma unroll
            for (int d = 1; d < 32; d <<= 1) {
                const int n = __shfl_up_sync(0xffffffffu, iw, d);
                if (t >= d) iw += n;
            }
            swsum[t] = iw - w;                 // exclusive warp base
        }
        __syncthreads();
        soff[t] = incl - v + swsum[t >> 5];    // exclusive prefix for bin t
        if (t == 0) soff[NB*NB] = NPTS;
    }
    __syncthreads();

    {
        const int pos = soff[pbin] + atomicAdd(&scur[pbin], 1);
        // s with the reference's rounding order (mul, mul, add)
        const float s = __fadd_rn(__fmul_rn(x, x), __fmul_rn(y, y));
        spts[pos] = make_float4(x, y, s, __int_as_float(t));
    }
    __syncthreads();

    // ---- Phase 2: split 5x5 neighborhood scan ----
    // Region reg: rx = reg & 7 (32 cells wide), ry = reg >> 3 (16 tall).
    // u = t & 511 indexes cells bin-major: binIdx = u>>6 (4x2 bins of 8x8 cells),
    // c = u & 63 inside the bin -> home bin warp-uniform (2 warps per bin).
    const int part = t >> 9;                   // 0: warps 0-15, 1: warps 16-31
    const int u    = t & 511;
    const int binI = u >> 6;
    const int cc   = u & 63;
    const int rx   = reg & 7, ry = reg >> 3;
    const int cx   = rx * 32 + (binI & 3) * 8 + (cc & 7);
    const int cy   = ry * 16 + (binI >> 2) * 8 + (cc >> 3);
    const int cell = cy * 256 + cx;
    const int bx   = cx >> 3;
    const int by   = cy >> 3;

    const float inv = 1.0f / 256.0f;
    const float gx = ((float)cx + 0.5f) * inv;
    const float gy = ((float)cy + 0.5f) * inv;
    const float g2 = gx * gx + gy * gy;        // geometry bound only

    unsigned long long bestk = 0xFFFFFFFFFFFFFFFFull;

    #define SCAN_RANGE(E0, E1)                                                  \
        _Pragma("unroll 2")                                                     \
        for (int k = (E0); k < (E1); ++k) {                                     \
            const float4 p = spts[k];                                           \
            const float dot = __fmaf_rn(p.y, gy, __fmul_rn(p.x, gx));           \
            const float d   = __fmaf_rn(-2.0f, dot, p.z);                       \
            unsigned int ub = __float_as_uint(d);                               \
            ub ^= (unsigned int)(((int)ub >> 31)) | 0x80000000u;                \
            const unsigned long long key =                                      \
                ((unsigned long long)ub << 32) | __float_as_uint(p.w);          \
            bestk = min(bestk, key);                                            \
        }

    // Clipped 5x5 neighborhood rows, split by part:
    //   part 0: yb in [max(by-2,0), by];  part 1: yb in [by+1, min(by+2, NB-1)].
    {
        const int xx0 = max(bx - 2, 0), xx1 = min(bx + 2, NB - 1);
        const int ys  = part ? (by + 1) : max(by - 2, 0);
        const int ye  = part ? min(by + 2, NB - 1) : by;
        for (int yb = ys; yb <= ye; ++yb) {
            const int e0 = soff[yb * NB + xx0];
            const int e1 = soff[yb * NB + xx1 + 1];
            SCAN_RANGE(e0, e1)
        }
    }

    // Merge part-1 partials into part-0 threads.
    if (part) skey[u] = bestk;
    __syncthreads();
    if (part) return;                          // part-1 warps done
    bestk = min(bestk, skey[u]);

    // Cold path: expanding rings r>=3 with rounding-safe termination (part 0).
    for (int r = 3; r < NB; ++r) {
        // Decode current best d2 (NaN if nothing scanned yet -> keep going).
        const unsigned int ob = (unsigned int)(bestk >> 32);
        const unsigned int fb = (ob & 0x80000000u) ? (ob ^ 0x80000000u) : ~ob;
        const float best = __uint_as_float(fb);
        // Distance to boundary of scanned square [bx-(r-1), bx+(r-1)]^2;
        // domain-edge faces excluded. Unscanned points have computed
        // d2 >= f^2 - g2 - eps; slack 1e-4 >> eps forbids beating OR tying,
        // so extra rings scanned for warp-mates can't change this thread.
        const float fL = (bx - (r - 1) >= 1)      ? (gx - (float)(bx - (r - 1)) * BINW) : 1e30f;
        const float fR = (bx + (r - 1) <= NB - 2) ? ((float)(bx + r) * BINW - gx)       : 1e30f;
        const float fB = (by - (r - 1) >= 1)      ? (gy - (float)(by - (r - 1)) * BINW) : 1e30f;
        const float fT = (by + (r - 1) <= NB - 2) ? ((float)(by + r) * BINW - gy)       : 1e30f;
        const float f  = fminf(fminf(fL, fR), fminf(fB, fT));
        const int cont = !(f * f > best + g2 + 1e-4f);      // NaN best -> cont
        if (!__any_sync(0xffffffffu, cont)) break;          // per-warp exit

        const int x0 = max(bx - r, 0), x1 = min(bx + r, NB - 1);
        const int y0 = max(by - r, 0), y1 = min(by + r, NB - 1);
        for (int yb = y0; yb <= y1; ++yb) {
            if (yb == by - r || yb == by + r) {
                const int e0 = soff[yb * NB + x0];
                const int e1 = soff[yb * NB + x1 + 1];
                SCAN_RANGE(e0, e1)
            } else {
                if (bx - r >= 0) {
                    const int bb = yb * NB + (bx - r);
                    SCAN_RANGE(soff[bb], soff[bb + 1])
                }
                if (bx + r <= NB - 1) {
                    const int bb = yb * NB + (bx + r);
                    SCAN_RANGE(soff[bb], soff[bb + 1])
                }
            }
        }
    }
    #undef SCAN_RANGE

    const int bi = (int)(bestk & 0xFFFFFFFFull);

    // ---- Phase 3: gather 4 channels from smem-staged R (part-0 threads) ----
    float* ob = out + b * (4 * 65536);
    #pragma unroll
    for (int c = 0; c < 4; ++c)
        ob[c * 65536 + cell] = sR[c * NPTS + bi];
}

extern "C" void kernel_launch(void* const* d_in, const int* in_sizes, int n_in,
                              void* d_out, int out_size) {
    const float* R  = (const float*)d_in[0];   // [2,4,1024]
    const float* XY = (const float*)d_in[1];   // [2,2,1024]
    float* out = (float*)d_out;                // [2,4,256,256]

    nn_fused<<<256, 1024>>>(XY, R, out);
}

// round 11
// speedup vs baseline: 1.1395x; 1.1395x over previous
#include <cuda_runtime.h>

// predictor_interp2d: nearest-neighbor gather from N=1024 points onto a 256x256 grid.
// d_in[0] = R_pc  [B=2, C=4, N=1024] float32
// d_in[1] = XY_pc [B=2, 2, N=1024]   float32
// d_out   = R_grd [B=2, C=4, 256, 256] float32
//
// Single fused kernel, 128 blocks x 1024 threads (one wave). Each block owns a
// 32x32-cell region (4x4 bins of 8x8 cells, NB=32) and builds a WINDOWED CSR:
// only points falling in the 8x8-bin window [region bins +/- 2] are scattered
// (avg ~64 of 1024), so the offset scan is a single-warp 64-bin scan and the
// atomics touch ~6% of threads. Each warp (2-bin pair, even base) scans the
// union 5-row x 6-col neighborhood with warp-uniform bounds (LDS broadcast).
// The rare cell whose rounding-safe bound is not met (prob ~3.5e-6) falls back
// to brute-forcing all 1024 points from global memory.
//
// Argmin is branch-free: key = (ordered_uint(d2) << 32) | point_index, reduced
// with u64 min == (min d2, then min index) == jnp.argmin first-min semantics.
// d2 uses the EXACT reference arithmetic (bit-matched since R2), so the result
// is bit-identical and scatter order is irrelevant.

#define NPTS  1024
#define NB    32
#define BINW  0.03125f

__global__ __launch_bounds__(1024, 1)
void nn_fused(const float* __restrict__ XY,
              const float* __restrict__ R,
              float* __restrict__ out) {
    __shared__ float4 wpts[NPTS];       // windowed points {px,py,s,idx-bits} (worst case all)
    __shared__ int    woff[65];         // window CSR offsets (8x8 bins)
    __shared__ int    wcnt[64];         // window bin counts
    __shared__ int    wcur[64];         // scatter cursors
    __shared__ float  sR[4 * NPTS];     // staged field values (16 KB)

    const int t   = threadIdx.x;
    const int b   = blockIdx.x >> 6;            // 64 regions per batch
    const int reg = blockIdx.x & 63;            // 8x8 regions of 32x32 cells
    const int qx  = reg & 7, qy = reg >> 3;
    const int bx0 = qx * 4, by0 = qy * 4;       // region's first bin
    const int wx0 = max(bx0 - 2, 0);            // window origin (8x8 bins)
    const int wy0 = max(by0 - 2, 0);

    // ---- Phase 1: windowed binning ----
    const float* xy = XY + b * (2 * NPTS);
    const float* Rb = R  + b * (4 * NPTS);

    if (t < 64) { wcnt[t] = 0; wcur[t] = 0; }

    // Stage R to smem (coalesced; latency overlapped with classification).
    #pragma unroll
    for (int c = 0; c < 4; ++c)
        sR[c * NPTS + t] = Rb[c * NPTS + t];
    __syncthreads();

    const float x = xy[t];
    const float y = xy[NPTS + t];
    const int bxx = min(max((int)(x * 32.0f), 0), NB - 1);
    const int byy = min(max((int)(y * 32.0f), 0), NB - 1);
    const int wx = bxx - wx0;
    const int wy = byy - wy0;
    const bool inw = ((unsigned)wx < 8u) && ((unsigned)wy < 8u);
    const int widx = wy * 8 + wx;
    if (inw) atomicAdd(&wcnt[widx], 1);
    __syncthreads();

    // Single-warp exclusive scan over 64 window bins (2 bins/lane).
    if (t < 32) {
        const int c0 = wcnt[t * 2], c1 = wcnt[t * 2 + 1];
        const int sum = c0 + c1;
        int incl = sum;
        #pragma unroll
        for (int d = 1; d < 32; d <<= 1) {
            const int n = __shfl_up_sync(0xffffffffu, incl, d);
            if (t >= d) incl += n;
        }
        const int base = incl - sum;
        woff[t * 2]     = base;
        woff[t * 2 + 1] = base + c0;
        if (t == 31) woff[64] = incl;
    }
    __syncthreads();

    if (inw) {
        const int pos = woff[widx] + atomicAdd(&wcur[widx], 1);
        // s with the reference's rounding order (mul, mul, add)
        const float s = __fadd_rn(__fmul_rn(x, x), __fmul_rn(y, y));
        wpts[pos] = make_float4(x, y, s, __int_as_float(t));
    }
    __syncthreads();

    // ---- Phase 2: warp-union neighborhood scan ----
    // sel = tile 0..3 (16x16 cells), u = t&255 within tile.
    // Warp = 32 consecutive u = 2 cell-rows x 16 cols -> by warp-uniform,
    // bx spans a 2-bin pair with even base bxw.
    const int sel = t >> 8;
    const int u   = t & 255;
    const int cx  = qx * 32 + (sel & 1) * 16 + (u & 15);
    const int cy  = qy * 32 + (sel >> 1) * 16 + (u >> 4);
    const int cell = cy * 256 + cx;
    const int bx  = cx >> 3;
    const int by  = cy >> 3;                    // warp-uniform
    const int bxw = bx & ~1;                    // even pair base, warp-uniform

    const float inv = 1.0f / 256.0f;
    const float gx = ((float)cx + 0.5f) * inv;
    const float gy = ((float)cy + 0.5f) * inv;
    const float g2 = gx * gx + gy * gy;         // geometry bound only

    unsigned long long bestk = 0xFFFFFFFFFFFFFFFFull;

    #define EVAL(PX, PY, PS, PI)                                                \
        {                                                                       \
            const float dot = __fmaf_rn((PY), gy, __fmul_rn((PX), gx));         \
            const float d   = __fmaf_rn(-2.0f, dot, (PS));                      \
            unsigned int ub = __float_as_uint(d);                               \
            ub ^= (unsigned int)(((int)ub >> 31)) | 0x80000000u;                \
            const unsigned long long key =                                      \
                ((unsigned long long)ub << 32) | (unsigned int)(PI);            \
            bestk = min(bestk, key);                                            \
        }

    // Union fast path: rows [by-2, by+2] (clipped), cols [bxw-2, bxw+3] (clipped).
    // Covers every lane's required 5x5; bounds warp-uniform; wpts reads broadcast.
    {
        const int xa = max(bxw - 2, 0)  - wx0;       // window-local col range
        const int xb = min(bxw + 3, NB - 1) - wx0;
        const int ya = max(by - 2, 0)   - wy0;
        const int yb_ = min(by + 2, NB - 1) - wy0;
        for (int yw = ya; yw <= yb_; ++yw) {
            const int e0 = woff[yw * 8 + xa];
            const int e1 = woff[yw * 8 + xb + 1];
            #pragma unroll 2
            for (int k = e0; k < e1; ++k) {
                const float4 p = wpts[k];
                EVAL(p.x, p.y, p.z, __float_as_uint(p.w))
            }
        }
    }

    // Cold fallback: if the rounding-safe bound fails for any lane, brute-force
    // all 1024 points from global. Scanned-for-sure square: radius 2 around own
    // home bin (domain-clipped faces excluded). Slack 1e-4 >> rounding eps
    // forbids unscanned points from beating OR tying the current winner.
    {
        const unsigned int ob = (unsigned int)(bestk >> 32);
        const unsigned int fb = (ob & 0x80000000u) ? (ob ^ 0x80000000u) : ~ob;
        const float best = __uint_as_float(fb);
        const float fL = (bx - 2 >= 1)      ? (gx - (float)(bx - 2) * BINW) : 1e30f;
        const float fR = (bx + 2 <= NB - 2) ? ((float)(bx + 3) * BINW - gx) : 1e30f;
        const float fB = (by - 2 >= 1)      ? (gy - (float)(by - 2) * BINW) : 1e30f;
        const float fT = (by + 2 <= NB - 2) ? ((float)(by + 3) * BINW - gy) : 1e30f;
        const float f  = fminf(fminf(fL, fR), fminf(fB, fT));
        const int cont = !(f * f > best + g2 + 1e-4f);      // NaN best -> cont
        if (__any_sync(0xffffffffu, cont)) {
            for (int k = 0; k < NPTS; ++k) {
                const float px = __ldg(&xy[k]);
                const float py = __ldg(&xy[NPTS + k]);
                const float ps = __fadd_rn(__fmul_rn(px, px), __fmul_rn(py, py));
                EVAL(px, py, ps, (unsigned int)k)
            }
        }
    }
    #undef EVAL

    const int bi = (int)(bestk & 0xFFFFFFFFull);

    // ---- Phase 3: gather 4 channels from smem-staged R ----
    float* ob = out + b * (4 * 65536);
    #pragma unroll
    for (int c = 0; c < 4; ++c)
        ob[c * 65536 + cell] = sR[c * NPTS + bi];
}

extern "C" void kernel_launch(void* const* d_in, const int* in_sizes, int n_in,
                              void* d_out, int out_size) {
    const float* R  = (const float*)d_in[0];   // [2,4,1024]
    const float* XY = (const float*)d_in[1];   // [2,2,1024]
    float* out = (float*)d_out;                // [2,4,256,256]

    nn_fused<<<128, 1024>>>(XY, R, out);
}